// round 1
// baseline (speedup 1.0000x reference)
#include <cuda_runtime.h>

#define N_ 16
#define C_ 128
#define H_ 128
#define W_ 128
#define HT 8          // output rows per depthwise block
#define HW_ (H_*W_)

// Scratch (allocation-free: __device__ globals)
__device__ __align__(16) float g_add[(size_t)N_*C_*H_*W_];
__device__ __align__(16) float g_w3t[C_*C_];

// ---------------------------------------------------------------------------
// packed f32x2 helpers (Blackwell FFMA2 path: full-rate fp32)
// ---------------------------------------------------------------------------
__device__ __forceinline__ unsigned long long pack2(float lo, float hi) {
    unsigned long long r;
    asm("mov.b64 %0, {%1, %2};"
        : "=l"(r) : "r"(__float_as_uint(lo)), "r"(__float_as_uint(hi)));
    return r;
}
__device__ __forceinline__ void fma2(unsigned long long& d,
                                     unsigned long long a,
                                     unsigned long long b) {
    asm("fma.rn.f32x2 %0, %1, %2, %3;" : "=l"(d) : "l"(a), "l"(b), "l"(d));
}
__device__ __forceinline__ float2 unpack2(unsigned long long v) {
    unsigned lo, hi;
    asm("mov.b64 {%0, %1}, %2;" : "=r"(lo), "=r"(hi) : "l"(v));
    return make_float2(__uint_as_float(lo), __uint_as_float(hi));
}

// ---------------------------------------------------------------------------
// Kernel 0: transpose w3 [o][c] -> g_w3t [c][o] so GEMM A-tile loads coalesce
// ---------------------------------------------------------------------------
__global__ void k_transpose(const float* __restrict__ w3) {
    int i = blockIdx.x * 256 + threadIdx.x;
    if (i < C_ * C_) {
        int o = i / C_, c = i % C_;
        g_w3t[c * C_ + o] = w3[o * C_ + c];
    }
}

// ---------------------------------------------------------------------------
// Kernel 1: fused depthwise stack -> g_add
//   add = conv3x3(x)+b0 + conv5x1(conv1x5(x)+b01)+b02 + conv11x1(conv1x11(x)+b11)+b12
// One block per (h-tile, c, n). Each thread owns one column w; horizontal conv
// results live in thread-private registers so the vertical taps are pure FMAs.
// ---------------------------------------------------------------------------
__global__ __launch_bounds__(128)
void k_dw(const float* __restrict__ x,
          const float* __restrict__ w0,  const float* __restrict__ b0,
          const float* __restrict__ w01, const float* __restrict__ b01,
          const float* __restrict__ w02, const float* __restrict__ b02,
          const float* __restrict__ w11, const float* __restrict__ b11,
          const float* __restrict__ w12, const float* __restrict__ b12)
{
    __shared__ __align__(16) float sx[HT + 10][144];   // 5-wide zero halo each side

    const int w  = threadIdx.x;
    const int h0 = blockIdx.x * HT;
    const int c  = blockIdx.y;
    const int n  = blockIdx.z;

    const float* xp = x + ((size_t)(n * C_ + c) * H_) * W_;

    #pragma unroll
    for (int i = 0; i < HT + 10; i++) {
        int gh = h0 - 5 + i;
        sx[i][5 + w] = (gh >= 0 && gh < H_) ? xp[gh * W_ + w] : 0.f;
        if (w < 5) { sx[i][w] = 0.f; sx[i][133 + w] = 0.f; }
    }
    __syncthreads();

    // per-channel weights in registers
    float kw0[9], kh5[5], kv5[5], kh11[11], kv11[11];
    #pragma unroll
    for (int j = 0; j < 9; j++)  kw0[j]  = w0[c * 9 + j];
    #pragma unroll
    for (int j = 0; j < 5; j++)  { kh5[j] = w01[c * 5 + j];  kv5[j]  = w02[c * 5 + j]; }
    #pragma unroll
    for (int j = 0; j < 11; j++) { kh11[j] = w11[c * 11 + j]; kv11[j] = w12[c * 11 + j]; }
    const float cb0 = b0[c], cb01 = b01[c], cb02 = b02[c], cb11 = b11[c], cb12 = b12[c];

    float h11col[HT + 10];   // horizontal 1x11 result per row (this column)
    float h5col [HT + 4];    // horizontal 1x5 result per row
    float acc33 [HT];
    #pragma unroll
    for (int k = 0; k < HT; k++) acc33[k] = 0.f;

    #pragma unroll
    for (int i = 0; i < HT + 10; i++) {
        int gh = h0 - 5 + i;
        bool valid = (gh >= 0 && gh < H_);   // out-of-range rows are ZERO padding
        float v[11];
        #pragma unroll
        for (int j = 0; j < 11; j++) v[j] = sx[i][w + j];  // x[gh][w-5+j]

        float s11 = cb11;
        #pragma unroll
        for (int j = 0; j < 11; j++) s11 = fmaf(v[j], kh11[j], s11);
        h11col[i] = valid ? s11 : 0.f;

        if (i >= 3 && i < HT + 7) {
            float s5 = cb01;
            #pragma unroll
            for (int j = 0; j < 5; j++) s5 = fmaf(v[3 + j], kh5[j], s5);
            h5col[i - 3] = valid ? s5 : 0.f;
        }

        // 3x3 contribution: output row k uses sx row k+4+dy  =>  k = i-4-dy
        #pragma unroll
        for (int dy = 0; dy < 3; dy++) {
            int k = i - 4 - dy;
            if (k >= 0 && k < HT) {
                acc33[k] = fmaf(v[4], kw0[dy * 3 + 0], acc33[k]);
                acc33[k] = fmaf(v[5], kw0[dy * 3 + 1], acc33[k]);
                acc33[k] = fmaf(v[6], kw0[dy * 3 + 2], acc33[k]);
            }
        }
    }

    float* ap = g_add + ((size_t)(n * C_ + c) * H_ + h0) * W_ + w;
    #pragma unroll
    for (int k = 0; k < HT; k++) {
        float s5 = cb02, s11 = cb12;
        #pragma unroll
        for (int j = 0; j < 5; j++)  s5  = fmaf(h5col[k + j],  kv5[j],  s5);
        #pragma unroll
        for (int j = 0; j < 11; j++) s11 = fmaf(h11col[k + j], kv11[j], s11);
        ap[k * W_] = acc33[k] + cb0 + s5 + s11;
    }
}

// ---------------------------------------------------------------------------
// Kernel 2: channel-mix GEMM + fused epilogue
//   out[n,o,p] = (sum_c w3[o,c] * add[n,c,p] + b3[o]) * x[n,o,p]
// BM=128(o) x BN=128(pixels) x BK=16, 256 threads, 8x8 micro-tile,
// inner product on packed fma.rn.f32x2 (FFMA2, full-rate fp32).
// ---------------------------------------------------------------------------
__global__ __launch_bounds__(256)
void k_mix(const float* __restrict__ x, const float* __restrict__ b3,
           float* __restrict__ out)
{
    __shared__ __align__(16) float As[16][128];   // w3t[c][o]
    __shared__ __align__(16) float Bs[16][128];   // add[c][p]

    const int tid = threadIdx.x;
    const int tx  = tid & 15;    // pixel group (8 px)
    const int ty  = tid >> 4;    // output-channel group (8 o)
    const int p0  = blockIdx.x * 128;
    const int n   = blockIdx.y;

    const float* addp = g_add + (size_t)n * C_ * HW_;

    unsigned long long acc[8][4];
    #pragma unroll
    for (int i = 0; i < 8; i++)
        #pragma unroll
        for (int j = 0; j < 4; j++) acc[i][j] = 0ull;

    for (int c0 = 0; c0 < C_; c0 += 16) {
        __syncthreads();
        #pragma unroll
        for (int i = 0; i < 2; i++) {
            int idx4 = tid + i * 256;           // 512 float4 per tile
            int k    = idx4 >> 5;
            int col  = (idx4 & 31) << 2;
            *(float4*)&As[k][col] = *(const float4*)&g_w3t[(c0 + k) * C_ + col];
            *(float4*)&Bs[k][col] = *(const float4*)&addp[(size_t)(c0 + k) * HW_ + p0 + col];
        }
        __syncthreads();

        #pragma unroll
        for (int k = 0; k < 16; k++) {
            float a[8], b[8];
            *(float4*)&a[0] = *(const float4*)&As[k][ty * 8];
            *(float4*)&a[4] = *(const float4*)&As[k][ty * 8 + 4];
            *(float4*)&b[0] = *(const float4*)&Bs[k][tx * 8];
            *(float4*)&b[4] = *(const float4*)&Bs[k][tx * 8 + 4];
            unsigned long long B2[4];
            #pragma unroll
            for (int j = 0; j < 4; j++) B2[j] = pack2(b[2 * j], b[2 * j + 1]);
            #pragma unroll
            for (int i = 0; i < 8; i++) {
                unsigned long long A2 = pack2(a[i], a[i]);
                #pragma unroll
                for (int j = 0; j < 4; j++) fma2(acc[i][j], A2, B2[j]);
            }
        }
    }

    // epilogue: (acc + b3) * x
    #pragma unroll
    for (int i = 0; i < 8; i++) {
        int o = ty * 8 + i;
        float bias = b3[o];
        const float* xp = x   + (size_t)(n * C_ + o) * HW_ + p0 + tx * 8;
        float*       op = out + (size_t)(n * C_ + o) * HW_ + p0 + tx * 8;
        #pragma unroll
        for (int j = 0; j < 4; j++) {
            float2 m  = unpack2(acc[i][j]);
            float2 xv = *(const float2*)&xp[2 * j];
            float2 r;
            r.x = (m.x + bias) * xv.x;
            r.y = (m.y + bias) * xv.y;
            *(float2*)&op[2 * j] = r;
        }
    }
}

// ---------------------------------------------------------------------------
extern "C" void kernel_launch(void* const* d_in, const int* in_sizes, int n_in,
                              void* d_out, int out_size)
{
    const float* x   = (const float*)d_in[0];
    const float* w0  = (const float*)d_in[1];
    const float* b0  = (const float*)d_in[2];
    const float* w01 = (const float*)d_in[3];
    const float* b01 = (const float*)d_in[4];
    const float* w02 = (const float*)d_in[5];
    const float* b02 = (const float*)d_in[6];
    const float* w11 = (const float*)d_in[7];
    const float* b11 = (const float*)d_in[8];
    const float* w12 = (const float*)d_in[9];
    const float* b12 = (const float*)d_in[10];
    const float* w3  = (const float*)d_in[11];
    const float* b3  = (const float*)d_in[12];
    float* out = (float*)d_out;

    k_transpose<<<64, 256>>>(w3);

    dim3 g1(H_ / HT, C_, N_);
    k_dw<<<g1, 128>>>(x, w0, b0, w01, b01, w02, b02, w11, b11, w12, b12);

    dim3 g2(HW_ / 128, N_);
    k_mix<<<g2, 256>>>(x, b3, out);
}

// round 3
// speedup vs baseline: 1.3136x; 1.3136x over previous
#include <cuda_runtime.h>
#include <cuda_bf16.h>
#include <cstdint>

#define N_ 16
#define C_ 128
#define H_ 128
#define W_ 128
#define HT 8
#define HW_ (H_*W_)

// Scratch (allocation-free: __device__ globals). add = hi + lo (bf16 split)
__device__ __align__(16) __nv_bfloat16 g_hi[(size_t)N_*C_*HW_];
__device__ __align__(16) __nv_bfloat16 g_lo[(size_t)N_*C_*HW_];

// ---------------------------------------------------------------------------
// helpers
// ---------------------------------------------------------------------------
__device__ __forceinline__ uint32_t smem_u32(const void* p) {
    uint32_t a;
    asm("{ .reg .u64 t; cvta.to.shared.u64 t, %1; cvt.u32.u64 %0, t; }" : "=r"(a) : "l"(p));
    return a;
}
__device__ __forceinline__ void cp16(uint32_t dst, const void* src) {
    asm volatile("cp.async.cg.shared.global [%0], [%1], 16;" :: "r"(dst), "l"(src) : "memory");
}
#define CP_COMMIT() asm volatile("cp.async.commit_group;" ::: "memory")
#define CP_WAIT(n)  asm volatile("cp.async.wait_group %0;" :: "n"(n) : "memory")

__device__ __forceinline__ void ldsm4(uint32_t* r, uint32_t a) {
    asm volatile("ldmatrix.sync.aligned.m8n8.x4.shared.b16 {%0,%1,%2,%3}, [%4];"
                 : "=r"(r[0]), "=r"(r[1]), "=r"(r[2]), "=r"(r[3]) : "r"(a));
}
__device__ __forceinline__ void ldsm4t(uint32_t* r, uint32_t a) {
    asm volatile("ldmatrix.sync.aligned.m8n8.x4.trans.shared.b16 {%0,%1,%2,%3}, [%4];"
                 : "=r"(r[0]), "=r"(r[1]), "=r"(r[2]), "=r"(r[3]) : "r"(a));
}
__device__ __forceinline__ void mma16816(float* d, const uint32_t* a, const uint32_t* b) {
    asm volatile("mma.sync.aligned.m16n8k16.row.col.f32.bf16.bf16.f32 "
        "{%0,%1,%2,%3}, {%4,%5,%6,%7}, {%8,%9}, {%0,%1,%2,%3};"
        : "+f"(d[0]), "+f"(d[1]), "+f"(d[2]), "+f"(d[3])
        : "r"(a[0]), "r"(a[1]), "r"(a[2]), "r"(a[3]), "r"(b[0]), "r"(b[1]));
}
__device__ __forceinline__ uint32_t bpack(__nv_bfloat16 a, __nv_bfloat16 b) {
    uint16_t ua = *(uint16_t*)&a, ub = *(uint16_t*)&b;
    return (uint32_t)ua | ((uint32_t)ub << 16);
}
__device__ __forceinline__ void split(float v, __nv_bfloat16& h, __nv_bfloat16& l) {
    h = __float2bfloat16(v);
    l = __float2bfloat16(v - __bfloat162float(h));
}

// ---------------------------------------------------------------------------
// Kernel 1: fused depthwise stack -> bf16 hi/lo planes (unchanged numerics)
// ---------------------------------------------------------------------------
__global__ __launch_bounds__(128)
void k_dw(const float* __restrict__ x,
          const float* __restrict__ w0,  const float* __restrict__ b0,
          const float* __restrict__ w01, const float* __restrict__ b01,
          const float* __restrict__ w02, const float* __restrict__ b02,
          const float* __restrict__ w11, const float* __restrict__ b11,
          const float* __restrict__ w12, const float* __restrict__ b12)
{
    __shared__ __align__(16) float sx[HT + 10][144];

    const int w  = threadIdx.x;
    const int h0 = blockIdx.x * HT;
    const int c  = blockIdx.y;
    const int n  = blockIdx.z;

    const float* xp = x + ((size_t)(n * C_ + c) * H_) * W_;

    #pragma unroll
    for (int i = 0; i < HT + 10; i++) {
        int gh = h0 - 5 + i;
        sx[i][5 + w] = (gh >= 0 && gh < H_) ? xp[gh * W_ + w] : 0.f;
        if (w < 5) { sx[i][w] = 0.f; sx[i][133 + w] = 0.f; }
    }
    __syncthreads();

    float kw0[9], kh5[5], kv5[5], kh11[11], kv11[11];
    #pragma unroll
    for (int j = 0; j < 9; j++)  kw0[j]  = w0[c * 9 + j];
    #pragma unroll
    for (int j = 0; j < 5; j++)  { kh5[j] = w01[c * 5 + j];  kv5[j]  = w02[c * 5 + j]; }
    #pragma unroll
    for (int j = 0; j < 11; j++) { kh11[j] = w11[c * 11 + j]; kv11[j] = w12[c * 11 + j]; }
    const float cb0 = b0[c], cb01 = b01[c], cb02 = b02[c], cb11 = b11[c], cb12 = b12[c];

    float h11col[HT + 10];
    float h5col [HT + 4];
    float acc33 [HT];
    #pragma unroll
    for (int k = 0; k < HT; k++) acc33[k] = 0.f;

    #pragma unroll
    for (int i = 0; i < HT + 10; i++) {
        int gh = h0 - 5 + i;
        bool valid = (gh >= 0 && gh < H_);
        float v[11];
        #pragma unroll
        for (int j = 0; j < 11; j++) v[j] = sx[i][w + j];

        float s11 = cb11;
        #pragma unroll
        for (int j = 0; j < 11; j++) s11 = fmaf(v[j], kh11[j], s11);
        h11col[i] = valid ? s11 : 0.f;

        if (i >= 3 && i < HT + 7) {
            float s5 = cb01;
            #pragma unroll
            for (int j = 0; j < 5; j++) s5 = fmaf(v[3 + j], kh5[j], s5);
            h5col[i - 3] = valid ? s5 : 0.f;
        }

        #pragma unroll
        for (int dy = 0; dy < 3; dy++) {
            int k = i - 4 - dy;
            if (k >= 0 && k < HT) {
                acc33[k] = fmaf(v[4], kw0[dy * 3 + 0], acc33[k]);
                acc33[k] = fmaf(v[5], kw0[dy * 3 + 1], acc33[k]);
                acc33[k] = fmaf(v[6], kw0[dy * 3 + 2], acc33[k]);
            }
        }
    }

    size_t base = ((size_t)(n * C_ + c) * H_ + h0) * W_ + w;
    #pragma unroll
    for (int k = 0; k < HT; k++) {
        float s5 = cb02, s11 = cb12;
        #pragma unroll
        for (int j = 0; j < 5; j++)  s5  = fmaf(h5col[k + j],  kv5[j],  s5);
        #pragma unroll
        for (int j = 0; j < 11; j++) s11 = fmaf(h11col[k + j], kv11[j], s11);
        float v = acc33[k] + cb0 + s5 + s11;
        __nv_bfloat16 h, l;
        split(v, h, l);
        g_hi[base + (size_t)k * W_] = h;
        g_lo[base + (size_t)k * W_] = l;
    }
}

// ---------------------------------------------------------------------------
// Kernel 2: mma.sync bf16 channel-mix GEMM + fused epilogue
//   D[o][p] = sum_c w3[o][c]*add[c][p]  via hi*hi + hi*lo + lo*hi
//   out[n][o][p] = (D + b3[o]) * x[n][o][p]
// Block: M=128(o) x N=64(px), K=128(c). 8 warps: warp_m in [0,4), warp_n in [0,2).
// A (w3) resident in smem per block; B double-buffered via cp.async.
// ---------------------------------------------------------------------------
#define TILE_N 64
#define TPB 8
// smem layout (bytes). A pitch 272B (128+8 halves), B pitch 144B (64+8 halves)
#define PA 272
#define PB 144
#define SM_A_HI 0
#define SM_A_LO (128*PA)                 // 34816
#define SM_B    (2*128*PA)               // 69632
#define B_PLANE (128*PB)                 // 18432
#define B_STAGE (2*B_PLANE)              // hi+lo per stage
#define SM_TOTAL (SM_B + 2*B_STAGE)      // 143360

__device__ __forceinline__ void load_B(uint32_t sb_stage, int tid, int n, int p0) {
    const __nv_bfloat16* hb = g_hi + (size_t)n * C_ * HW_ + p0;
    const __nv_bfloat16* lb = g_lo + (size_t)n * C_ * HW_ + p0;
    // 128 rows x 8 chunks(16B) per plane = 1024 chunks; 256 threads -> 4 each
    #pragma unroll
    for (int i = 0; i < 4; i++) {
        int lin = i * 256 + tid;
        int c = lin >> 3, ch = lin & 7;
        uint32_t dst = sb_stage + (uint32_t)(c * PB + ch * 16);
        cp16(dst,           hb + (size_t)c * HW_ + ch * 8);
        cp16(dst + B_PLANE, lb + (size_t)c * HW_ + ch * 8);
    }
    CP_COMMIT();
}

__global__ __launch_bounds__(256, 1)
void k_mix_mma(const float* __restrict__ x, const float* __restrict__ w3,
               const float* __restrict__ b3, float* __restrict__ out)
{
    extern __shared__ char smem[];
    const uint32_t sb = smem_u32(smem);
    const int tid  = threadIdx.x;
    const int lane = tid & 31;
    const int wid  = tid >> 5;
    const int warp_m = wid & 3;          // 4 warps over o
    const int warp_n = wid >> 2;         // 2 warps over px
    const int m0 = warp_m * 32;
    const int n0 = warp_n * 32;
    const int lm16 = lane & 15;
    const int co8  = (lane >> 4) * 8;    // half-element col offset

    // ---- load A = w3 -> smem bf16 hi/lo, row-major [o][c], pitch PA ----
    #pragma unroll
    for (int i = 0; i < 16; i++) {
        int idx = i * 256 + tid;         // 4096 float4
        int o = idx >> 5;
        int c4 = (idx & 31) << 2;
        float4 v = *(const float4*)&w3[o * C_ + c4];
        __nv_bfloat16 h0, h1, h2, h3, l0, l1, l2, l3;
        split(v.x, h0, l0); split(v.y, h1, l1);
        split(v.z, h2, l2); split(v.w, h3, l3);
        uint32_t off = (uint32_t)(o * PA + c4 * 2);
        *(uint2*)(smem + SM_A_HI + off) = make_uint2(bpack(h0, h1), bpack(h2, h3));
        *(uint2*)(smem + SM_A_LO + off) = make_uint2(bpack(l0, l1), bpack(l2, l3));
    }

    // bias per thread (rows owned by this warp's frags)
    float bias[2][2];
    #pragma unroll
    for (int i = 0; i < 2; i++) {
        bias[i][0] = b3[m0 + i * 16 + (lane >> 2)];
        bias[i][1] = b3[m0 + i * 16 + (lane >> 2) + 8];
    }

    // prefetch tile 0
    {
        int tile0 = blockIdx.x * TPB;
        load_B(sb + SM_B, tid, tile0 >> 8, (tile0 & 255) * TILE_N);
    }

    for (int t = 0; t < TPB; t++) {
        const int tile = blockIdx.x * TPB + t;
        const int n  = tile >> 8;
        const int p0 = (tile & 255) * TILE_N;
        const uint32_t sBst = sb + SM_B + (uint32_t)(t & 1) * B_STAGE;

        if (t + 1 < TPB) {
            int nt = tile + 1;
            load_B(sb + SM_B + (uint32_t)((t + 1) & 1) * B_STAGE, tid,
                   nt >> 8, (nt & 255) * TILE_N);
            CP_WAIT(1);
        } else {
            CP_WAIT(0);
        }
        __syncthreads();

        float acc[2][4][4];
        #pragma unroll
        for (int i = 0; i < 2; i++)
            #pragma unroll
            for (int j = 0; j < 4; j++)
                #pragma unroll
                for (int q = 0; q < 4; q++) acc[i][j][q] = 0.f;

        #pragma unroll
        for (int ks = 0; ks < 8; ks++) {
            const int c0 = ks * 16;
            uint32_t ah[2][4], al[2][4], bh[2][4], bl[2][4];
            uint32_t arow = (uint32_t)((m0 + lm16) * PA + (c0 + co8) * 2);
            ldsm4(ah[0], sb + SM_A_HI + arow);
            ldsm4(ah[1], sb + SM_A_HI + arow + 16 * PA);
            ldsm4(al[0], sb + SM_A_LO + arow);
            ldsm4(al[1], sb + SM_A_LO + arow + 16 * PA);
            uint32_t brow = (uint32_t)((c0 + lm16) * PB + (n0 + co8) * 2);
            ldsm4t(bh[0], sBst + brow);
            ldsm4t(bh[1], sBst + brow + 32);           // +16 px
            ldsm4t(bl[0], sBst + B_PLANE + brow);
            ldsm4t(bl[1], sBst + B_PLANE + brow + 32);

            #pragma unroll
            for (int i = 0; i < 2; i++)
                #pragma unroll
                for (int j = 0; j < 4; j++) {
                    const uint32_t* bhf = &bh[j >> 1][(j & 1) * 2];
                    const uint32_t* blf = &bl[j >> 1][(j & 1) * 2];
                    mma16816(acc[i][j], ah[i], bhf);
                    mma16816(acc[i][j], ah[i], blf);
                    mma16816(acc[i][j], al[i], bhf);
                }
        }

        // epilogue: (acc + b3) * x -> out
        #pragma unroll
        for (int i = 0; i < 2; i++) {
            #pragma unroll
            for (int j = 0; j < 4; j++) {
                int o_r = m0 + i * 16 + (lane >> 2);
                int px  = p0 + n0 + j * 8 + (lane & 3) * 2;
                size_t base0 = ((size_t)(n * C_ + o_r)) * HW_ + px;
                float2 xv0 = *(const float2*)&x[base0];
                float2 xv1 = *(const float2*)&x[base0 + 8 * HW_];
                float2 r0, r1;
                r0.x = (acc[i][j][0] + bias[i][0]) * xv0.x;
                r0.y = (acc[i][j][1] + bias[i][0]) * xv0.y;
                r1.x = (acc[i][j][2] + bias[i][1]) * xv1.x;
                r1.y = (acc[i][j][3] + bias[i][1]) * xv1.y;
                *(float2*)&out[base0]           = r0;
                *(float2*)&out[base0 + 8 * HW_] = r1;
            }
        }
        __syncthreads();   // protect B stage before next prefetch overwrites
    }
}

// ---------------------------------------------------------------------------
extern "C" void kernel_launch(void* const* d_in, const int* in_sizes, int n_in,
                              void* d_out, int out_size)
{
    const float* x   = (const float*)d_in[0];
    const float* w0  = (const float*)d_in[1];
    const float* b0  = (const float*)d_in[2];
    const float* w01 = (const float*)d_in[3];
    const float* b01 = (const float*)d_in[4];
    const float* w02 = (const float*)d_in[5];
    const float* b02 = (const float*)d_in[6];
    const float* w11 = (const float*)d_in[7];
    const float* b11 = (const float*)d_in[8];
    const float* w12 = (const float*)d_in[9];
    const float* b12 = (const float*)d_in[10];
    const float* w3  = (const float*)d_in[11];
    const float* b3  = (const float*)d_in[12];
    float* out = (float*)d_out;

    cudaFuncSetAttribute(k_mix_mma, cudaFuncAttributeMaxDynamicSharedMemorySize, SM_TOTAL);

    dim3 g1(H_ / HT, C_, N_);
    k_dw<<<g1, 128>>>(x, w0, b0, w01, b01, w02, b02, w11, b11, w12, b12);

    int tiles = N_ * (HW_ / TILE_N);        // 4096
    k_mix_mma<<<tiles / TPB, 256, SM_TOTAL>>>(x, w3, b3, out);
}

// round 4
// speedup vs baseline: 1.6963x; 1.2914x over previous
#include <cuda_runtime.h>
#include <cuda_bf16.h>
#include <cstdint>

#define N_ 16
#define C_ 128
#define H_ 128
#define W_ 128
#define HW_ (H_*W_)

// Scratch (allocation-free: __device__ globals). add = hi + lo (bf16 split)
__device__ __align__(16) __nv_bfloat16 g_hi[(size_t)N_*C_*HW_];
__device__ __align__(16) __nv_bfloat16 g_lo[(size_t)N_*C_*HW_];

typedef unsigned long long ull;

// ---------------------------------------------------------------------------
// helpers
// ---------------------------------------------------------------------------
__device__ __forceinline__ uint32_t smem_u32(const void* p) {
    uint32_t a;
    asm("{ .reg .u64 t; cvta.to.shared.u64 t, %1; cvt.u32.u64 %0, t; }" : "=r"(a) : "l"(p));
    return a;
}
__device__ __forceinline__ void cp16(uint32_t dst, const void* src) {
    asm volatile("cp.async.cg.shared.global [%0], [%1], 16;" :: "r"(dst), "l"(src) : "memory");
}
#define CP_COMMIT() asm volatile("cp.async.commit_group;" ::: "memory")
#define CP_WAIT(n)  asm volatile("cp.async.wait_group %0;" :: "n"(n) : "memory")

__device__ __forceinline__ void ldsm4(uint32_t* r, uint32_t a) {
    asm volatile("ldmatrix.sync.aligned.m8n8.x4.shared.b16 {%0,%1,%2,%3}, [%4];"
                 : "=r"(r[0]), "=r"(r[1]), "=r"(r[2]), "=r"(r[3]) : "r"(a));
}
__device__ __forceinline__ void ldsm4t(uint32_t* r, uint32_t a) {
    asm volatile("ldmatrix.sync.aligned.m8n8.x4.trans.shared.b16 {%0,%1,%2,%3}, [%4];"
                 : "=r"(r[0]), "=r"(r[1]), "=r"(r[2]), "=r"(r[3]) : "r"(a));
}
__device__ __forceinline__ void mma16816(float* d, const uint32_t* a, const uint32_t* b) {
    asm volatile("mma.sync.aligned.m16n8k16.row.col.f32.bf16.bf16.f32 "
        "{%0,%1,%2,%3}, {%4,%5,%6,%7}, {%8,%9}, {%0,%1,%2,%3};"
        : "+f"(d[0]), "+f"(d[1]), "+f"(d[2]), "+f"(d[3])
        : "r"(a[0]), "r"(a[1]), "r"(a[2]), "r"(a[3]), "r"(b[0]), "r"(b[1]));
}
__device__ __forceinline__ uint32_t bpack(__nv_bfloat16 a, __nv_bfloat16 b) {
    uint16_t ua = *(uint16_t*)&a, ub = *(uint16_t*)&b;
    return (uint32_t)ua | ((uint32_t)ub << 16);
}
__device__ __forceinline__ void split(float v, __nv_bfloat16& h, __nv_bfloat16& l) {
    h = __float2bfloat16(v);
    l = __float2bfloat16(v - __bfloat162float(h));
}
__device__ __forceinline__ ull pack2(float lo, float hi) {
    ull r;
    asm("mov.b64 %0, {%1, %2};"
        : "=l"(r) : "r"(__float_as_uint(lo)), "r"(__float_as_uint(hi)));
    return r;
}
__device__ __forceinline__ void fma2(ull& d, ull a, ull b) {
    asm("fma.rn.f32x2 %0, %1, %2, %3;" : "=l"(d) : "l"(a), "l"(b), "l"(d));
}
__device__ __forceinline__ float2 unpack2(ull v) {
    unsigned lo, hi;
    asm("mov.b64 {%0, %1}, %2;" : "=r"(lo), "=r"(hi) : "l"(v));
    return make_float2(__uint_as_float(lo), __uint_as_float(hi));
}

// ---------------------------------------------------------------------------
// Kernel 1: fused depthwise stack -> bf16 hi/lo planes, packed f32x2 math.
// Block (64,2): thread owns column pair (2tx,2tx+1), ty picks 8-row subtile.
// Block covers 16 output rows. Scatter-accumulate per input row.
// ---------------------------------------------------------------------------
__global__ __launch_bounds__(128)
void k_dw(const float* __restrict__ x,
          const float* __restrict__ w0,  const float* __restrict__ b0,
          const float* __restrict__ w01, const float* __restrict__ b01,
          const float* __restrict__ w02, const float* __restrict__ b02,
          const float* __restrict__ w11, const float* __restrict__ b11,
          const float* __restrict__ w12, const float* __restrict__ b12)
{
    __shared__ __align__(16) float sx[26][144];

    const int tx = threadIdx.x;          // 0..63
    const int ty = threadIdx.y;          // 0..1
    const int tid = ty * 64 + tx;
    const int h0 = blockIdx.x * 16;
    const int c  = blockIdx.y;
    const int n  = blockIdx.z;

    // load 26 input rows (h0-5 .. h0+20) with zero padding
    {
        const float* xp = x + (size_t)(n * C_ + c) * HW_;
        int w = tid;
        #pragma unroll
        for (int i = 0; i < 26; i++) {
            int gh = h0 - 5 + i;
            sx[i][5 + w] = (gh >= 0 && gh < H_) ? xp[gh * W_ + w] : 0.f;
            if (w < 5) { sx[i][w] = 0.f; sx[i][133 + w] = 0.f; }
        }
    }
    __syncthreads();

    // packed per-channel weights
    ull kw0p[9], kh5p[5], kv5p[5], kh11p[11], kv11p[11];
    #pragma unroll
    for (int j = 0; j < 9; j++)  { float v = w0[c * 9 + j];  kw0p[j]  = pack2(v, v); }
    #pragma unroll
    for (int j = 0; j < 5; j++)  { float a = w01[c * 5 + j], b = w02[c * 5 + j];
                                   kh5p[j] = pack2(a, a); kv5p[j] = pack2(b, b); }
    #pragma unroll
    for (int j = 0; j < 11; j++) { float a = w11[c * 11 + j], b = w12[c * 11 + j];
                                   kh11p[j] = pack2(a, a); kv11p[j] = pack2(b, b); }
    const float cb0 = b0[c], cb01 = b01[c], cb02 = b02[c], cb11 = b11[c], cb12 = b12[c];
    const ull cb01p = pack2(cb01, cb01);
    const ull cb11p = pack2(cb11, cb11);

    ull acc11[8], acc5[8], acc33[8];
    #pragma unroll
    for (int k = 0; k < 8; k++) { acc11[k] = 0ull; acc5[k] = 0ull; acc33[k] = 0ull; }

    const int c2 = tx * 2;

    #pragma unroll
    for (int i = 0; i < 18; i++) {
        const int srow = ty * 8 + i;
        const int gh = h0 + ty * 8 + i - 5;
        const bool valid = (gh >= 0 && gh < H_);

        float2 q[6];
        #pragma unroll
        for (int m = 0; m < 6; m++) q[m] = *(const float2*)&sx[srow][c2 + 2 * m];

        ull p[11];
        #pragma unroll
        for (int m = 0; m < 6; m++) {
            if (2 * m < 11) p[2 * m] = pack2(q[m].x, q[m].y);
        }
        #pragma unroll
        for (int m = 0; m < 5; m++) p[2 * m + 1] = pack2(q[m].y, q[m + 1].x);

        // 1x11 horizontal
        ull h11 = cb11p;
        #pragma unroll
        for (int j = 0; j < 11; j++) fma2(h11, p[j], kh11p[j]);
        if (!valid) h11 = 0ull;
        #pragma unroll
        for (int k = 0; k < 8; k++) {
            if (i - k >= 0 && i - k <= 10) fma2(acc11[k], h11, kv11p[i - k]);
        }

        // 1x5 horizontal (rows i=3..14)
        if (i >= 3 && i <= 14) {
            ull h5 = cb01p;
            #pragma unroll
            for (int j = 0; j < 5; j++) fma2(h5, p[3 + j], kh5p[j]);
            if (!valid) h5 = 0ull;
            const int i3 = i - 3;
            #pragma unroll
            for (int k = 0; k < 8; k++) {
                if (i3 - k >= 0 && i3 - k <= 4) fma2(acc5[k], h5, kv5p[i3 - k]);
            }
        }

        // 3x3 (zero-padded sx rows contribute zero automatically)
        if (i >= 4 && i <= 13) {
            #pragma unroll
            for (int dy = 0; dy < 3; dy++) {
                const int k = i - 4 - dy;
                if (k >= 0 && k < 8) {
                    fma2(acc33[k], p[4], kw0p[dy * 3 + 0]);
                    fma2(acc33[k], p[5], kw0p[dy * 3 + 1]);
                    fma2(acc33[k], p[6], kw0p[dy * 3 + 2]);
                }
            }
        }
    }

    const float cbs = cb0 + cb02 + cb12;
    size_t base = ((size_t)(n * C_ + c) * H_ + h0 + ty * 8) * W_ + c2;
    #pragma unroll
    for (int k = 0; k < 8; k++) {
        float2 a3 = unpack2(acc33[k]), a5 = unpack2(acc5[k]), a11 = unpack2(acc11[k]);
        float v0 = a3.x + a5.x + a11.x + cbs;
        float v1 = a3.y + a5.y + a11.y + cbs;
        __nv_bfloat16 h0b, l0b, h1b, l1b;
        split(v0, h0b, l0b);
        split(v1, h1b, l1b);
        *(uint32_t*)&g_hi[base + (size_t)k * W_] = bpack(h0b, h1b);
        *(uint32_t*)&g_lo[base + (size_t)k * W_] = bpack(l0b, l1b);
    }
}

// ---------------------------------------------------------------------------
// Kernel 2: mma.sync bf16 channel-mix GEMM + fused epilogue, 512 threads.
//   D[o][p] = sum_c w3[o][c]*add[c][p]  via hi*hi + hi*lo + lo*hi
//   out[n][o][p] = (D + b3[o]) * x[n][o][p]
// Block tile M=128(o) x N=64(px) x K=128(c). 16 warps: 4(m) x 4(n),
// warp tile 32o x 16px. A resident; B double-buffered cp.async.
// ---------------------------------------------------------------------------
#define TILE_N 64
#define TPB 8
#define PA 272
#define PB 144
#define SM_A_HI 0
#define SM_A_LO (128*PA)
#define SM_B    (2*128*PA)
#define B_PLANE (128*PB)
#define B_STAGE (2*B_PLANE)
#define SM_TOTAL (SM_B + 2*B_STAGE)      // 143360

__device__ __forceinline__ void load_B(uint32_t sb_stage, int tid, int n, int p0) {
    const __nv_bfloat16* hb = g_hi + (size_t)n * C_ * HW_ + p0;
    const __nv_bfloat16* lb = g_lo + (size_t)n * C_ * HW_ + p0;
    // 1024 16B-chunks per plane; 512 threads -> 2 iterations
    #pragma unroll
    for (int i = 0; i < 2; i++) {
        int lin = i * 512 + tid;
        int c = lin >> 3, ch = lin & 7;
        uint32_t dst = sb_stage + (uint32_t)(c * PB + ch * 16);
        cp16(dst,           hb + (size_t)c * HW_ + ch * 8);
        cp16(dst + B_PLANE, lb + (size_t)c * HW_ + ch * 8);
    }
    CP_COMMIT();
}

__global__ __launch_bounds__(512, 1)
void k_mix_mma(const float* __restrict__ x, const float* __restrict__ w3,
               const float* __restrict__ b3, float* __restrict__ out)
{
    extern __shared__ char smem[];
    const uint32_t sb = smem_u32(smem);
    const int tid  = threadIdx.x;
    const int lane = tid & 31;
    const int wid  = tid >> 5;
    const int warp_m = wid & 3;          // 4 warps over o   (32 each)
    const int warp_n = wid >> 2;         // 4 warps over px  (16 each)
    const int m0 = warp_m * 32;
    const int n0 = warp_n * 16;
    const int lm16 = lane & 15;
    const int co8  = (lane >> 4) * 8;

    // ---- load A = w3 -> smem bf16 hi/lo, row-major [o][c], pitch PA ----
    #pragma unroll
    for (int i = 0; i < 8; i++) {
        int idx = i * 512 + tid;         // 4096 float4
        int o = idx >> 5;
        int c4 = (idx & 31) << 2;
        float4 v = *(const float4*)&w3[o * C_ + c4];
        __nv_bfloat16 h0, h1, h2, h3, l0, l1, l2, l3;
        split(v.x, h0, l0); split(v.y, h1, l1);
        split(v.z, h2, l2); split(v.w, h3, l3);
        uint32_t off = (uint32_t)(o * PA + c4 * 2);
        *(uint2*)(smem + SM_A_HI + off) = make_uint2(bpack(h0, h1), bpack(h2, h3));
        *(uint2*)(smem + SM_A_LO + off) = make_uint2(bpack(l0, l1), bpack(l2, l3));
    }

    float bias[2][2];
    #pragma unroll
    for (int i = 0; i < 2; i++) {
        bias[i][0] = b3[m0 + i * 16 + (lane >> 2)];
        bias[i][1] = b3[m0 + i * 16 + (lane >> 2) + 8];
    }

    // prefetch tile 0
    {
        int tile0 = blockIdx.x * TPB;
        load_B(sb + SM_B, tid, tile0 >> 8, (tile0 & 255) * TILE_N);
    }

    for (int t = 0; t < TPB; t++) {
        const int tile = blockIdx.x * TPB + t;
        const int n  = tile >> 8;
        const int p0 = (tile & 255) * TILE_N;
        const uint32_t sBst = sb + SM_B + (uint32_t)(t & 1) * B_STAGE;

        if (t + 1 < TPB) {
            int nt = tile + 1;
            load_B(sb + SM_B + (uint32_t)((t + 1) & 1) * B_STAGE, tid,
                   nt >> 8, (nt & 255) * TILE_N);
            CP_WAIT(1);
        } else {
            CP_WAIT(0);
        }
        __syncthreads();

        float acc[2][2][4];
        #pragma unroll
        for (int i = 0; i < 2; i++)
            #pragma unroll
            for (int j = 0; j < 2; j++)
                #pragma unroll
                for (int q = 0; q < 4; q++) acc[i][j][q] = 0.f;

        #pragma unroll
        for (int ks = 0; ks < 8; ks++) {
            const int c0 = ks * 16;
            uint32_t ah[2][4], al[2][4], bh[4], bl[4];
            uint32_t arow = (uint32_t)((m0 + lm16) * PA + (c0 + co8) * 2);
            ldsm4(ah[0], sb + SM_A_HI + arow);
            ldsm4(ah[1], sb + SM_A_HI + arow + 16 * PA);
            ldsm4(al[0], sb + SM_A_LO + arow);
            ldsm4(al[1], sb + SM_A_LO + arow + 16 * PA);
            uint32_t brow = (uint32_t)((c0 + lm16) * PB + (n0 + co8) * 2);
            ldsm4t(bh, sBst + brow);
            ldsm4t(bl, sBst + B_PLANE + brow);

            #pragma unroll
            for (int i = 0; i < 2; i++)
                #pragma unroll
                for (int j = 0; j < 2; j++) {
                    const uint32_t* bhf = &bh[j * 2];
                    const uint32_t* blf = &bl[j * 2];
                    mma16816(acc[i][j], ah[i], bhf);
                    mma16816(acc[i][j], ah[i], blf);
                    mma16816(acc[i][j], al[i], bhf);
                }
        }

        // epilogue: (acc + b3) * x -> out
        #pragma unroll
        for (int i = 0; i < 2; i++) {
            #pragma unroll
            for (int j = 0; j < 2; j++) {
                int o_r = m0 + i * 16 + (lane >> 2);
                int px  = p0 + n0 + j * 8 + (lane & 3) * 2;
                size_t base0 = ((size_t)(n * C_ + o_r)) * HW_ + px;
                float2 xv0 = *(const float2*)&x[base0];
                float2 xv1 = *(const float2*)&x[base0 + 8 * HW_];
                float2 r0, r1;
                r0.x = (acc[i][j][0] + bias[i][0]) * xv0.x;
                r0.y = (acc[i][j][1] + bias[i][0]) * xv0.y;
                r1.x = (acc[i][j][2] + bias[i][1]) * xv1.x;
                r1.y = (acc[i][j][3] + bias[i][1]) * xv1.y;
                *(float2*)&out[base0]           = r0;
                *(float2*)&out[base0 + 8 * HW_] = r1;
            }
        }
        __syncthreads();   // protect B stage before next prefetch overwrites
    }
}

// ---------------------------------------------------------------------------
extern "C" void kernel_launch(void* const* d_in, const int* in_sizes, int n_in,
                              void* d_out, int out_size)
{
    const float* x   = (const float*)d_in[0];
    const float* w0  = (const float*)d_in[1];
    const float* b0  = (const float*)d_in[2];
    const float* w01 = (const float*)d_in[3];
    const float* b01 = (const float*)d_in[4];
    const float* w02 = (const float*)d_in[5];
    const float* b02 = (const float*)d_in[6];
    const float* w11 = (const float*)d_in[7];
    const float* b11 = (const float*)d_in[8];
    const float* w12 = (const float*)d_in[9];
    const float* b12 = (const float*)d_in[10];
    const float* w3  = (const float*)d_in[11];
    const float* b3  = (const float*)d_in[12];
    float* out = (float*)d_out;

    cudaFuncSetAttribute(k_mix_mma, cudaFuncAttributeMaxDynamicSharedMemorySize, SM_TOTAL);

    dim3 g1(H_ / 16, C_, N_);
    k_dw<<<g1, dim3(64, 2)>>>(x, w0, b0, w01, b01, w02, b02, w11, b11, w12, b12);

    int tiles = N_ * (HW_ / TILE_N);        // 4096
    k_mix_mma<<<tiles / TPB, 512, SM_TOTAL>>>(x, w3, b3, out);
}

// round 5
// speedup vs baseline: 1.7160x; 1.0116x over previous
#include <cuda_runtime.h>
#include <cuda_bf16.h>
#include <cstdint>

#define N_ 16
#define C_ 128
#define H_ 128
#define W_ 128
#define HW_ (H_*W_)

// Scratch (allocation-free: __device__ globals). add = hi + lo (bf16 split)
__device__ __align__(16) __nv_bfloat16 g_hi[(size_t)N_*C_*HW_];
__device__ __align__(16) __nv_bfloat16 g_lo[(size_t)N_*C_*HW_];

typedef unsigned long long ull;

// ---------------------------------------------------------------------------
// helpers
// ---------------------------------------------------------------------------
__device__ __forceinline__ uint32_t smem_u32(const void* p) {
    uint32_t a;
    asm("{ .reg .u64 t; cvta.to.shared.u64 t, %1; cvt.u32.u64 %0, t; }" : "=r"(a) : "l"(p));
    return a;
}
__device__ __forceinline__ void cp16(uint32_t dst, const void* src) {
    asm volatile("cp.async.cg.shared.global [%0], [%1], 16;" :: "r"(dst), "l"(src) : "memory");
}
#define CP_COMMIT() asm volatile("cp.async.commit_group;" ::: "memory")
#define CP_WAIT(n)  asm volatile("cp.async.wait_group %0;" :: "n"(n) : "memory")

__device__ __forceinline__ void ldsm4(uint32_t* r, uint32_t a) {
    asm volatile("ldmatrix.sync.aligned.m8n8.x4.shared.b16 {%0,%1,%2,%3}, [%4];"
                 : "=r"(r[0]), "=r"(r[1]), "=r"(r[2]), "=r"(r[3]) : "r"(a));
}
__device__ __forceinline__ void ldsm4t(uint32_t* r, uint32_t a) {
    asm volatile("ldmatrix.sync.aligned.m8n8.x4.trans.shared.b16 {%0,%1,%2,%3}, [%4];"
                 : "=r"(r[0]), "=r"(r[1]), "=r"(r[2]), "=r"(r[3]) : "r"(a));
}
__device__ __forceinline__ void mma16816(float* d, const uint32_t* a, const uint32_t* b) {
    asm volatile("mma.sync.aligned.m16n8k16.row.col.f32.bf16.bf16.f32 "
        "{%0,%1,%2,%3}, {%4,%5,%6,%7}, {%8,%9}, {%0,%1,%2,%3};"
        : "+f"(d[0]), "+f"(d[1]), "+f"(d[2]), "+f"(d[3])
        : "r"(a[0]), "r"(a[1]), "r"(a[2]), "r"(a[3]), "r"(b[0]), "r"(b[1]));
}
__device__ __forceinline__ uint32_t bpack(__nv_bfloat16 a, __nv_bfloat16 b) {
    uint16_t ua = *(uint16_t*)&a, ub = *(uint16_t*)&b;
    return (uint32_t)ua | ((uint32_t)ub << 16);
}
__device__ __forceinline__ void split(float v, __nv_bfloat16& h, __nv_bfloat16& l) {
    h = __float2bfloat16(v);
    l = __float2bfloat16(v - __bfloat162float(h));
}
__device__ __forceinline__ ull pack2(float lo, float hi) {
    ull r;
    asm("mov.b64 %0, {%1, %2};"
        : "=l"(r) : "r"(__float_as_uint(lo)), "r"(__float_as_uint(hi)));
    return r;
}
__device__ __forceinline__ void fma2(ull& d, ull a, ull b) {
    asm("fma.rn.f32x2 %0, %1, %2, %3;" : "=l"(d) : "l"(a), "l"(b), "l"(d));
}
__device__ __forceinline__ float2 unpack2(ull v) {
    unsigned lo, hi;
    asm("mov.b64 {%0, %1}, %2;" : "=r"(lo), "=r"(hi) : "l"(v));
    return make_float2(__uint_as_float(lo), __uint_as_float(hi));
}

// ---------------------------------------------------------------------------
// Kernel 1: fused depthwise stack -> bf16 hi/lo planes, packed f32x2 math.
// (unchanged from round 4)
// ---------------------------------------------------------------------------
__global__ __launch_bounds__(128)
void k_dw(const float* __restrict__ x,
          const float* __restrict__ w0,  const float* __restrict__ b0,
          const float* __restrict__ w01, const float* __restrict__ b01,
          const float* __restrict__ w02, const float* __restrict__ b02,
          const float* __restrict__ w11, const float* __restrict__ b11,
          const float* __restrict__ w12, const float* __restrict__ b12)
{
    __shared__ __align__(16) float sx[26][144];

    const int tx = threadIdx.x;          // 0..63
    const int ty = threadIdx.y;          // 0..1
    const int tid = ty * 64 + tx;
    const int h0 = blockIdx.x * 16;
    const int c  = blockIdx.y;
    const int n  = blockIdx.z;

    {
        const float* xp = x + (size_t)(n * C_ + c) * HW_;
        int w = tid;
        #pragma unroll
        for (int i = 0; i < 26; i++) {
            int gh = h0 - 5 + i;
            sx[i][5 + w] = (gh >= 0 && gh < H_) ? xp[gh * W_ + w] : 0.f;
            if (w < 5) { sx[i][w] = 0.f; sx[i][133 + w] = 0.f; }
        }
    }
    __syncthreads();

    ull kw0p[9], kh5p[5], kv5p[5], kh11p[11], kv11p[11];
    #pragma unroll
    for (int j = 0; j < 9; j++)  { float v = w0[c * 9 + j];  kw0p[j]  = pack2(v, v); }
    #pragma unroll
    for (int j = 0; j < 5; j++)  { float a = w01[c * 5 + j], b = w02[c * 5 + j];
                                   kh5p[j] = pack2(a, a); kv5p[j] = pack2(b, b); }
    #pragma unroll
    for (int j = 0; j < 11; j++) { float a = w11[c * 11 + j], b = w12[c * 11 + j];
                                   kh11p[j] = pack2(a, a); kv11p[j] = pack2(b, b); }
    const float cb0 = b0[c], cb01 = b01[c], cb02 = b02[c], cb11 = b11[c], cb12 = b12[c];
    const ull cb01p = pack2(cb01, cb01);
    const ull cb11p = pack2(cb11, cb11);

    ull acc11[8], acc5[8], acc33[8];
    #pragma unroll
    for (int k = 0; k < 8; k++) { acc11[k] = 0ull; acc5[k] = 0ull; acc33[k] = 0ull; }

    const int c2 = tx * 2;

    #pragma unroll
    for (int i = 0; i < 18; i++) {
        const int srow = ty * 8 + i;
        const int gh = h0 + ty * 8 + i - 5;
        const bool valid = (gh >= 0 && gh < H_);

        float2 q[6];
        #pragma unroll
        for (int m = 0; m < 6; m++) q[m] = *(const float2*)&sx[srow][c2 + 2 * m];

        ull p[11];
        #pragma unroll
        for (int m = 0; m < 6; m++) {
            if (2 * m < 11) p[2 * m] = pack2(q[m].x, q[m].y);
        }
        #pragma unroll
        for (int m = 0; m < 5; m++) p[2 * m + 1] = pack2(q[m].y, q[m + 1].x);

        ull h11 = cb11p;
        #pragma unroll
        for (int j = 0; j < 11; j++) fma2(h11, p[j], kh11p[j]);
        if (!valid) h11 = 0ull;
        #pragma unroll
        for (int k = 0; k < 8; k++) {
            if (i - k >= 0 && i - k <= 10) fma2(acc11[k], h11, kv11p[i - k]);
        }

        if (i >= 3 && i <= 14) {
            ull h5 = cb01p;
            #pragma unroll
            for (int j = 0; j < 5; j++) fma2(h5, p[3 + j], kh5p[j]);
            if (!valid) h5 = 0ull;
            const int i3 = i - 3;
            #pragma unroll
            for (int k = 0; k < 8; k++) {
                if (i3 - k >= 0 && i3 - k <= 4) fma2(acc5[k], h5, kv5p[i3 - k]);
            }
        }

        if (i >= 4 && i <= 13) {
            #pragma unroll
            for (int dy = 0; dy < 3; dy++) {
                const int k = i - 4 - dy;
                if (k >= 0 && k < 8) {
                    fma2(acc33[k], p[4], kw0p[dy * 3 + 0]);
                    fma2(acc33[k], p[5], kw0p[dy * 3 + 1]);
                    fma2(acc33[k], p[6], kw0p[dy * 3 + 2]);
                }
            }
        }
    }

    const float cbs = cb0 + cb02 + cb12;
    size_t base = ((size_t)(n * C_ + c) * H_ + h0 + ty * 8) * W_ + c2;
    #pragma unroll
    for (int k = 0; k < 8; k++) {
        float2 a3 = unpack2(acc33[k]), a5 = unpack2(acc5[k]), a11 = unpack2(acc11[k]);
        float v0 = a3.x + a5.x + a11.x + cbs;
        float v1 = a3.y + a5.y + a11.y + cbs;
        __nv_bfloat16 h0b, l0b, h1b, l1b;
        split(v0, h0b, l0b);
        split(v1, h1b, l1b);
        *(uint32_t*)&g_hi[base + (size_t)k * W_] = bpack(h0b, h1b);
        *(uint32_t*)&g_lo[base + (size_t)k * W_] = bpack(l0b, l1b);
    }
}

// ---------------------------------------------------------------------------
// Kernel 2: mma.sync bf16 channel-mix GEMM + fused epilogue, 512 threads.
// Software-pipelined: 3-stage B ring (2 cp.async groups in flight), epilogue
// x prefetched into registers before the MMA loop, ONE barrier per iteration.
// ---------------------------------------------------------------------------
#define TILE_N 64
#define TPB 8
#define NSTAGE 3
#define PA 272
#define PB 144
#define SM_A_HI 0
#define SM_A_LO (128*PA)
#define SM_B    (2*128*PA)
#define B_PLANE (128*PB)
#define B_STAGE (2*B_PLANE)
#define SM_TOTAL (SM_B + NSTAGE*B_STAGE)   // 69632 + 110592 = 180224

__device__ __forceinline__ void load_B(uint32_t sb_stage, int tid, int n, int p0) {
    const __nv_bfloat16* hb = g_hi + (size_t)n * C_ * HW_ + p0;
    const __nv_bfloat16* lb = g_lo + (size_t)n * C_ * HW_ + p0;
    #pragma unroll
    for (int i = 0; i < 2; i++) {
        int lin = i * 512 + tid;
        int c = lin >> 3, ch = lin & 7;
        uint32_t dst = sb_stage + (uint32_t)(c * PB + ch * 16);
        cp16(dst,           hb + (size_t)c * HW_ + ch * 8);
        cp16(dst + B_PLANE, lb + (size_t)c * HW_ + ch * 8);
    }
    CP_COMMIT();
}

__global__ __launch_bounds__(512, 1)
void k_mix_mma(const float* __restrict__ x, const float* __restrict__ w3,
               const float* __restrict__ b3, float* __restrict__ out)
{
    extern __shared__ char smem[];
    const uint32_t sb = smem_u32(smem);
    const int tid  = threadIdx.x;
    const int lane = tid & 31;
    const int wid  = tid >> 5;
    const int warp_m = wid & 3;          // 4 warps over o   (32 each)
    const int warp_n = wid >> 2;         // 4 warps over px  (16 each)
    const int m0 = warp_m * 32;
    const int n0 = warp_n * 16;
    const int lm16 = lane & 15;
    const int co8  = (lane >> 4) * 8;

    // ---- load A = w3 -> smem bf16 hi/lo, row-major [o][c], pitch PA ----
    #pragma unroll
    for (int i = 0; i < 8; i++) {
        int idx = i * 512 + tid;
        int o = idx >> 5;
        int c4 = (idx & 31) << 2;
        float4 v = *(const float4*)&w3[o * C_ + c4];
        __nv_bfloat16 h0, h1, h2, h3, l0, l1, l2, l3;
        split(v.x, h0, l0); split(v.y, h1, l1);
        split(v.z, h2, l2); split(v.w, h3, l3);
        uint32_t off = (uint32_t)(o * PA + c4 * 2);
        *(uint2*)(smem + SM_A_HI + off) = make_uint2(bpack(h0, h1), bpack(h2, h3));
        *(uint2*)(smem + SM_A_LO + off) = make_uint2(bpack(l0, l1), bpack(l2, l3));
    }

    float bias[2][2];
    #pragma unroll
    for (int i = 0; i < 2; i++) {
        bias[i][0] = b3[m0 + i * 16 + (lane >> 2)];
        bias[i][1] = b3[m0 + i * 16 + (lane >> 2) + 8];
    }

    // prologue: prefetch B for tiles 0 and 1
    {
        int tile0 = blockIdx.x * TPB;
        load_B(sb + SM_B + 0 * B_STAGE, tid, tile0 >> 8, (tile0 & 255) * TILE_N);
        int tile1 = tile0 + 1;
        load_B(sb + SM_B + 1 * B_STAGE, tid, tile1 >> 8, (tile1 & 255) * TILE_N);
    }

    int stage = 0;
    for (int t = 0; t < TPB; t++) {
        const int tile = blockIdx.x * TPB + t;
        const int n  = tile >> 8;
        const int p0 = (tile & 255) * TILE_N;
        const uint32_t sBst = sb + SM_B + (uint32_t)stage * B_STAGE;

        // ---- prefetch epilogue x into registers (overlaps everything) ----
        float2 xv[2][2][2];
        #pragma unroll
        for (int i = 0; i < 2; i++) {
            #pragma unroll
            for (int j = 0; j < 2; j++) {
                int o_r = m0 + i * 16 + (lane >> 2);
                int px  = p0 + n0 + j * 8 + (lane & 3) * 2;
                size_t base0 = ((size_t)(n * C_ + o_r)) * HW_ + px;
                xv[i][j][0] = *(const float2*)&x[base0];
                xv[i][j][1] = *(const float2*)&x[base0 + 8 * HW_];
            }
        }

        // wait for this tile's B; barrier also proves stage (t+2)%3 is free
        if (t < TPB - 1) { CP_WAIT(1); } else { CP_WAIT(0); }
        __syncthreads();

        // issue B prefetch for tile t+2 into the just-freed stage
        if (t + 2 < TPB) {
            int nt = tile + 2;
            int nstage = stage + 2; if (nstage >= NSTAGE) nstage -= NSTAGE;
            load_B(sb + SM_B + (uint32_t)nstage * B_STAGE, tid,
                   nt >> 8, (nt & 255) * TILE_N);
        }

        float acc[2][2][4];
        #pragma unroll
        for (int i = 0; i < 2; i++)
            #pragma unroll
            for (int j = 0; j < 2; j++)
                #pragma unroll
                for (int q = 0; q < 4; q++) acc[i][j][q] = 0.f;

        #pragma unroll
        for (int ks = 0; ks < 8; ks++) {
            const int c0 = ks * 16;
            uint32_t ah[2][4], al[2][4], bh[4], bl[4];
            uint32_t arow = (uint32_t)((m0 + lm16) * PA + (c0 + co8) * 2);
            ldsm4(ah[0], sb + SM_A_HI + arow);
            ldsm4(ah[1], sb + SM_A_HI + arow + 16 * PA);
            ldsm4(al[0], sb + SM_A_LO + arow);
            ldsm4(al[1], sb + SM_A_LO + arow + 16 * PA);
            uint32_t brow = (uint32_t)((c0 + lm16) * PB + (n0 + co8) * 2);
            ldsm4t(bh, sBst + brow);
            ldsm4t(bl, sBst + B_PLANE + brow);

            #pragma unroll
            for (int i = 0; i < 2; i++)
                #pragma unroll
                for (int j = 0; j < 2; j++) {
                    const uint32_t* bhf = &bh[j * 2];
                    const uint32_t* blf = &bl[j * 2];
                    mma16816(acc[i][j], ah[i], bhf);
                    mma16816(acc[i][j], ah[i], blf);
                    mma16816(acc[i][j], al[i], bhf);
                }
        }

        // epilogue: (acc + b3) * x -> out  (x already in registers)
        #pragma unroll
        for (int i = 0; i < 2; i++) {
            #pragma unroll
            for (int j = 0; j < 2; j++) {
                int o_r = m0 + i * 16 + (lane >> 2);
                int px  = p0 + n0 + j * 8 + (lane & 3) * 2;
                size_t base0 = ((size_t)(n * C_ + o_r)) * HW_ + px;
                float2 r0, r1;
                r0.x = (acc[i][j][0] + bias[i][0]) * xv[i][j][0].x;
                r0.y = (acc[i][j][1] + bias[i][0]) * xv[i][j][0].y;
                r1.x = (acc[i][j][2] + bias[i][1]) * xv[i][j][1].x;
                r1.y = (acc[i][j][3] + bias[i][1]) * xv[i][j][1].y;
                *(float2*)&out[base0]           = r0;
                *(float2*)&out[base0 + 8 * HW_] = r1;
            }
        }

        if (++stage >= NSTAGE) stage = 0;
    }
}

// ---------------------------------------------------------------------------
extern "C" void kernel_launch(void* const* d_in, const int* in_sizes, int n_in,
                              void* d_out, int out_size)
{
    const float* x   = (const float*)d_in[0];
    const float* w0  = (const float*)d_in[1];
    const float* b0  = (const float*)d_in[2];
    const float* w01 = (const float*)d_in[3];
    const float* b01 = (const float*)d_in[4];
    const float* w02 = (const float*)d_in[5];
    const float* b02 = (const float*)d_in[6];
    const float* w11 = (const float*)d_in[7];
    const float* b11 = (const float*)d_in[8];
    const float* w12 = (const float*)d_in[9];
    const float* b12 = (const float*)d_in[10];
    const float* w3  = (const float*)d_in[11];
    const float* b3  = (const float*)d_in[12];
    float* out = (float*)d_out;

    cudaFuncSetAttribute(k_mix_mma, cudaFuncAttributeMaxDynamicSharedMemorySize, SM_TOTAL);

    dim3 g1(H_ / 16, C_, N_);
    k_dw<<<g1, dim3(64, 2)>>>(x, w0, b0, w01, b01, w02, b02, w11, b11, w12, b12);

    int tiles = N_ * (HW_ / TILE_N);        // 4096
    k_mix_mma<<<tiles / TPB, 512, SM_TOTAL>>>(x, w3, b3, out);
}